// round 3
// baseline (speedup 1.0000x reference)
#include <cuda_runtime.h>
#include <cuda_bf16.h>

#define LSE_EPS 1e-5f
#define LSE_ITER 4

// Folded parameters: W1f[16] (o*4+c), t1[4] @16, W2f[32] @20 (o*4+c), t2[8] @52
__device__ float g_params[60];

__global__ void lse_fold_params(const float* __restrict__ W1, const float* __restrict__ g1,
                                const float* __restrict__ b1, const float* __restrict__ m1,
                                const float* __restrict__ v1,
                                const float* __restrict__ W2, const float* __restrict__ g2,
                                const float* __restrict__ b2, const float* __restrict__ m2,
                                const float* __restrict__ v2) {
    int i = threadIdx.x;
    if (i < 4) {
        float s = g1[i] * rsqrtf(v1[i] + LSE_EPS);
        #pragma unroll
        for (int c = 0; c < 4; c++) g_params[i * 4 + c] = W1[i * 4 + c] * s;
        g_params[16 + i] = b1[i] - m1[i] * s;
    }
    if (i < 8) {
        float s = g2[i] * rsqrtf(v2[i] + LSE_EPS);
        #pragma unroll
        for (int c = 0; c < 4; c++) g_params[20 + i * 4 + c] = W2[i * 4 + c] * s;
        g_params[52 + i] = b2[i] - m2[i] * s;
    }
}

__device__ __forceinline__ void lse_compute_store(float nx, float ny, float nz,
                                                  float cx, float cy, float cz,
                                                  const float* __restrict__ W1f,
                                                  const float* __restrict__ t1,
                                                  const float* __restrict__ W2f,
                                                  const float* __restrict__ t2,
                                                  float* __restrict__ out, int g) {
    float rx = nx - cx;
    float ry = ny - cy;
    float rz = nz - cz;
    float d  = sqrtf(fmaf(rx, rx, fmaf(ry, ry, rz * rz)));

    float h[4];
    #pragma unroll
    for (int o = 0; o < 4; o++) {
        float acc = t1[o];
        acc = fmaf(rx, W1f[o * 4 + 0], acc);
        acc = fmaf(ry, W1f[o * 4 + 1], acc);
        acc = fmaf(rz, W1f[o * 4 + 2], acc);
        acc = fmaf(d,  W1f[o * 4 + 3], acc);
        h[o] = fmaxf(acc, 0.0f);
    }

    float r[8];
    #pragma unroll
    for (int o = 0; o < 8; o++) {
        float acc = t2[o];
        acc = fmaf(h[0], W2f[o * 4 + 0], acc);
        acc = fmaf(h[1], W2f[o * 4 + 1], acc);
        acc = fmaf(h[2], W2f[o * 4 + 2], acc);
        acc = fmaf(h[3], W2f[o * 4 + 3], acc);
        r[o] = fmaxf(acc, 0.0f);
    }

    float4* ob = reinterpret_cast<float4*>(out + (size_t)g * 8);
    ob[0] = make_float4(r[0], r[1], r[2], r[3]);
    ob[1] = make_float4(r[4], r[5], r[6], r[7]);
}

// Thread-per-neighbor, 4 neighbors/thread strided by blockDim (warp-dense
// global access). All 24 loads for the 4 iterations are issued up front so
// DRAM latency is covered by MLP instead of occupancy.
__global__ __launch_bounds__(256) void lse_main(const float* __restrict__ coords,
                                                const float* __restrict__ nbr,
                                                float* __restrict__ out,
                                                int total_nb) {
    __shared__ float sp[60];
    if (threadIdx.x < 60) sp[threadIdx.x] = g_params[threadIdx.x];

    int base = blockIdx.x * (256 * LSE_ITER) + threadIdx.x;

    if (base + 256 * (LSE_ITER - 1) < total_nb) {
        // Fast path: batch-issue all global loads before the barrier.
        float nx[LSE_ITER], ny[LSE_ITER], nz[LSE_ITER];
        float cx[LSE_ITER], cy[LSE_ITER], cz[LSE_ITER];
        #pragma unroll
        for (int it = 0; it < LSE_ITER; it++) {
            int g = base + it * 256;
            const float* p = nbr + (size_t)g * 3;
            nx[it] = __ldg(p + 0);
            ny[it] = __ldg(p + 1);
            nz[it] = __ldg(p + 2);
            int bn = g >> 4;
            const float* q = coords + (size_t)bn * 3;
            cx[it] = __ldg(q + 0);
            cy[it] = __ldg(q + 1);
            cz[it] = __ldg(q + 2);
        }

        __syncthreads();
        float W1f[16], t1[4], W2f[32], t2[8];
        #pragma unroll
        for (int i = 0; i < 16; i++) W1f[i] = sp[i];
        #pragma unroll
        for (int i = 0; i < 4; i++) t1[i] = sp[16 + i];
        #pragma unroll
        for (int i = 0; i < 32; i++) W2f[i] = sp[20 + i];
        #pragma unroll
        for (int i = 0; i < 8; i++) t2[i] = sp[52 + i];

        #pragma unroll
        for (int it = 0; it < LSE_ITER; it++) {
            lse_compute_store(nx[it], ny[it], nz[it], cx[it], cy[it], cz[it],
                              W1f, t1, W2f, t2, out, base + it * 256);
        }
    } else {
        // Tail path (not taken for the benchmark shape).
        __syncthreads();
        float W1f[16], t1[4], W2f[32], t2[8];
        #pragma unroll
        for (int i = 0; i < 16; i++) W1f[i] = sp[i];
        #pragma unroll
        for (int i = 0; i < 4; i++) t1[i] = sp[16 + i];
        #pragma unroll
        for (int i = 0; i < 32; i++) W2f[i] = sp[20 + i];
        #pragma unroll
        for (int i = 0; i < 8; i++) t2[i] = sp[52 + i];

        for (int it = 0; it < LSE_ITER; it++) {
            int g = base + it * 256;
            if (g < total_nb) {
                const float* p = nbr + (size_t)g * 3;
                int bn = g >> 4;
                const float* q = coords + (size_t)bn * 3;
                lse_compute_store(__ldg(p), __ldg(p + 1), __ldg(p + 2),
                                  __ldg(q), __ldg(q + 1), __ldg(q + 2),
                                  W1f, t1, W2f, t2, out, g);
            }
        }
    }
}

extern "C" void kernel_launch(void* const* d_in, const int* in_sizes, int n_in,
                              void* d_out, int out_size) {
    const float* coords = (const float*)d_in[0];   // (B,N,3)
    const float* nbr    = (const float*)d_in[1];   // (B,N,K,3)
    const float* W1 = (const float*)d_in[2];
    const float* g1 = (const float*)d_in[3];
    const float* b1 = (const float*)d_in[4];
    const float* m1 = (const float*)d_in[5];
    const float* v1 = (const float*)d_in[6];
    const float* W2 = (const float*)d_in[7];
    const float* g2 = (const float*)d_in[8];
    const float* b2 = (const float*)d_in[9];
    const float* m2 = (const float*)d_in[10];
    const float* v2 = (const float*)d_in[11];
    float* out = (float*)d_out;

    int total_nb = (in_sizes[0] / 3) * 16;   // B*N*K = 2,097,152

    lse_fold_params<<<1, 32>>>(W1, g1, b1, m1, v1, W2, g2, b2, m2, v2);

    int threads = 256;
    int per_block = threads * LSE_ITER;
    int blocks = (total_nb + per_block - 1) / per_block;
    lse_main<<<blocks, threads>>>(coords, nbr, out, total_nb);
}

// round 5
// speedup vs baseline: 1.0727x; 1.0727x over previous
#include <cuda_runtime.h>
#include <cuda_bf16.h>

#define LSE_EPS 1e-5f
#define LSE_ITER 4

// Folded parameters: W1f[16] (o*4+c), t1[4] @16, W2f[32] @20 (o*4+c), t2[8] @52
__device__   float g_params[60];
__constant__ float c_params[60];

__global__ void lse_fold_params(const float* __restrict__ W1, const float* __restrict__ g1,
                                const float* __restrict__ b1, const float* __restrict__ m1,
                                const float* __restrict__ v1,
                                const float* __restrict__ W2, const float* __restrict__ g2,
                                const float* __restrict__ b2, const float* __restrict__ m2,
                                const float* __restrict__ v2) {
    int i = threadIdx.x;
    if (i < 4) {
        float s = g1[i] * rsqrtf(v1[i] + LSE_EPS);
        #pragma unroll
        for (int c = 0; c < 4; c++) g_params[i * 4 + c] = W1[i * 4 + c] * s;
        g_params[16 + i] = b1[i] - m1[i] * s;
    }
    if (i < 8) {
        float s = g2[i] * rsqrtf(v2[i] + LSE_EPS);
        #pragma unroll
        for (int c = 0; c < 4; c++) g_params[20 + i * 4 + c] = W2[i * 4 + c] * s;
        g_params[52 + i] = b2[i] - m2[i] * s;
    }
}

// Params come from __constant__ (uniform LDCU -> UR operands on sm_103a), so
// they cost no GPR space and no per-thread load traffic.
__device__ __forceinline__ void lse_compute_store(float nx, float ny, float nz,
                                                  float cx, float cy, float cz,
                                                  float* __restrict__ out, int g) {
    float rx = nx - cx;
    float ry = ny - cy;
    float rz = nz - cz;
    float d  = sqrtf(fmaf(rx, rx, fmaf(ry, ry, rz * rz)));

    float h[4];
    #pragma unroll
    for (int o = 0; o < 4; o++) {
        float acc = c_params[16 + o];
        acc = fmaf(rx, c_params[o * 4 + 0], acc);
        acc = fmaf(ry, c_params[o * 4 + 1], acc);
        acc = fmaf(rz, c_params[o * 4 + 2], acc);
        acc = fmaf(d,  c_params[o * 4 + 3], acc);
        h[o] = fmaxf(acc, 0.0f);
    }

    float r[8];
    #pragma unroll
    for (int o = 0; o < 8; o++) {
        float acc = c_params[52 + o];
        acc = fmaf(h[0], c_params[20 + o * 4 + 0], acc);
        acc = fmaf(h[1], c_params[20 + o * 4 + 1], acc);
        acc = fmaf(h[2], c_params[20 + o * 4 + 2], acc);
        acc = fmaf(h[3], c_params[20 + o * 4 + 3], acc);
        r[o] = fmaxf(acc, 0.0f);
    }

    float4* ob = reinterpret_cast<float4*>(out + (size_t)g * 8);
    ob[0] = make_float4(r[0], r[1], r[2], r[3]);
    ob[1] = make_float4(r[4], r[5], r[6], r[7]);
}

// Thread-per-neighbor, 4 neighbors/thread strided by blockDim (warp-dense
// global access). All 24 loads batched up front for MLP; occupancy forced to
// >=4 blocks/SM now that params are constant-bank resident.
__global__ __launch_bounds__(256, 4) void lse_main(const float* __restrict__ coords,
                                                   const float* __restrict__ nbr,
                                                   float* __restrict__ out,
                                                   int total_nb) {
    int base = blockIdx.x * (256 * LSE_ITER) + threadIdx.x;

    if (base + 256 * (LSE_ITER - 1) < total_nb) {
        float nx[LSE_ITER], ny[LSE_ITER], nz[LSE_ITER];
        float cx[LSE_ITER], cy[LSE_ITER], cz[LSE_ITER];
        #pragma unroll
        for (int it = 0; it < LSE_ITER; it++) {
            int g = base + it * 256;
            const float* p = nbr + (size_t)g * 3;
            nx[it] = __ldg(p + 0);
            ny[it] = __ldg(p + 1);
            nz[it] = __ldg(p + 2);
            int bn = g >> 4;
            const float* q = coords + (size_t)bn * 3;
            cx[it] = __ldg(q + 0);
            cy[it] = __ldg(q + 1);
            cz[it] = __ldg(q + 2);
        }

        #pragma unroll
        for (int it = 0; it < LSE_ITER; it++) {
            lse_compute_store(nx[it], ny[it], nz[it], cx[it], cy[it], cz[it],
                              out, base + it * 256);
        }
    } else {
        // Tail path (not taken for the benchmark shape).
        for (int it = 0; it < LSE_ITER; it++) {
            int g = base + it * 256;
            if (g < total_nb) {
                const float* p = nbr + (size_t)g * 3;
                int bn = g >> 4;
                const float* q = coords + (size_t)bn * 3;
                lse_compute_store(__ldg(p), __ldg(p + 1), __ldg(p + 2),
                                  __ldg(q), __ldg(q + 1), __ldg(q + 2),
                                  out, g);
            }
        }
    }
}

extern "C" void kernel_launch(void* const* d_in, const int* in_sizes, int n_in,
                              void* d_out, int out_size) {
    const float* coords = (const float*)d_in[0];   // (B,N,3)
    const float* nbr    = (const float*)d_in[1];   // (B,N,K,3)
    const float* W1 = (const float*)d_in[2];
    const float* g1 = (const float*)d_in[3];
    const float* b1 = (const float*)d_in[4];
    const float* m1 = (const float*)d_in[5];
    const float* v1 = (const float*)d_in[6];
    const float* W2 = (const float*)d_in[7];
    const float* g2 = (const float*)d_in[8];
    const float* b2 = (const float*)d_in[9];
    const float* m2 = (const float*)d_in[10];
    const float* v2 = (const float*)d_in[11];
    float* out = (float*)d_out;

    int total_nb = (in_sizes[0] / 3) * 16;   // B*N*K = 2,097,152

    lse_fold_params<<<1, 32>>>(W1, g1, b1, m1, v1, W2, g2, b2, m2, v2);

    // Stage folded params into the constant bank (graph-capturable D2D memcpy).
    void* src = nullptr;
    cudaGetSymbolAddress(&src, g_params);
    cudaMemcpyToSymbolAsync(c_params, src, 60 * sizeof(float), 0,
                            cudaMemcpyDeviceToDevice, 0);

    int threads = 256;
    int per_block = threads * LSE_ITER;
    int blocks = (total_nb + per_block - 1) / per_block;
    lse_main<<<blocks, threads>>>(coords, nbr, out, total_nb);
}